// round 5
// baseline (speedup 1.0000x reference)
#include <cuda_runtime.h>

typedef unsigned long long u64;

// ---------------- packed f32x2 helpers (Blackwell FFMA2) ----------------
__device__ __forceinline__ u64 pack2(float a, float b) {
    u64 r; asm("mov.b64 %0, {%1, %2};" : "=l"(r) : "f"(a), "f"(b)); return r;
}
__device__ __forceinline__ u64 pack1(float a) { return pack2(a, a); }
__device__ __forceinline__ void unpack2(u64 v, float& a, float& b) {
    asm("mov.b64 {%0, %1}, %2;" : "=f"(a), "=f"(b) : "l"(v));
}
__device__ __forceinline__ u64 fma2(u64 a, u64 b, u64 c) {
    u64 d; asm("fma.rn.f32x2 %0, %1, %2, %3;" : "=l"(d) : "l"(a), "l"(b), "l"(c));
    return d;
}
__device__ __forceinline__ u64 relu2(u64 v) {
    float a, b; unpack2(v, a, b);
    a = fmaxf(a, 0.0f); b = fmaxf(b, 0.0f);
    return pack2(a, b);
}

// ---------------- constants ----------------
#define NTHREADS 256
#define ROWS_PER_THREAD 4
#define PAIRS 2
static constexpr int BATCH = 2097152;
static constexpr int CHUNK = BATCH / ROWS_PER_THREAD;  // 524288

// ---------------- padded weight table (u64 indices), bias embedded -------
// stage1 fused: 5 rows, stride 10: [w0..w7, b, pad]       [0,50)
// W2..W4:       5 rows, stride 6:  [w0..w4, b]            [50,80) [80,110) [110,140)
// W5:           4 rows, stride 6:  [w0..w4, b]            [140,164)
#define OFF_FW   0
#define OFF_W2   50
#define OFF_W3   80
#define OFF_W4   110
#define OFF_W5   140
#define W_TOTAL  164

// compute fused/padded table entry t directly from raw weights
__device__ __forceinline__ float table_entry(
    int t,
    const float* __restrict__ W0, const float* __restrict__ b0,
    const float* __restrict__ W1, const float* __restrict__ b1,
    const float* __restrict__ W2, const float* __restrict__ b2,
    const float* __restrict__ W3, const float* __restrict__ b3,
    const float* __restrict__ W4, const float* __restrict__ b4,
    const float* __restrict__ W5, const float* __restrict__ b5) {
    if (t < 50) {
        int o = t / 10, k = t % 10;
        if (k < 8) {
            float s = 0.0f;
#pragma unroll
            for (int h = 0; h < 5; h++) s += W1[o * 5 + h] * W0[h * 8 + k];
            return s;
        } else if (k == 8) {
            float s = b1[o];
#pragma unroll
            for (int h = 0; h < 5; h++) s += W1[o * 5 + h] * b0[h];
            return s;
        }
        return 0.0f;
    } else if (t < 80) {
        int i = t - OFF_W2, o = i / 6, k = i % 6;
        return (k < 5) ? W2[o * 5 + k] : b2[o];
    } else if (t < 110) {
        int i = t - OFF_W3, o = i / 6, k = i % 6;
        return (k < 5) ? W3[o * 5 + k] : b3[o];
    } else if (t < 140) {
        int i = t - OFF_W4, o = i / 6, k = i % 6;
        return (k < 5) ? W4[o * 5 + k] : b4[o];
    } else {
        int i = t - OFF_W5, o = i / 6, k = i % 6;
        return (k < 5) ? W5[o * 5 + k] : b5[o];
    }
}

// one hidden stage (5 -> relu(5)): 3x LDS.128 per neuron row (weights+bias),
// each row applied to both pairs
__device__ __forceinline__ void hidden_stage(u64 a[PAIRS][5], const u64* sw, int woff) {
    u64 h[PAIRS][5];
#pragma unroll
    for (int o = 0; o < 5; o++) {
        ulonglong2 wa = *reinterpret_cast<const ulonglong2*>(sw + woff + o * 6);
        ulonglong2 wb = *reinterpret_cast<const ulonglong2*>(sw + woff + o * 6 + 2);
        ulonglong2 wc = *reinterpret_cast<const ulonglong2*>(sw + woff + o * 6 + 4);
#pragma unroll
        for (int p = 0; p < PAIRS; p++) {
            u64 acc = wc.y;  // bias
            acc = fma2(a[p][0], wa.x, acc);
            acc = fma2(a[p][1], wa.y, acc);
            acc = fma2(a[p][2], wb.x, acc);
            acc = fma2(a[p][3], wb.y, acc);
            acc = fma2(a[p][4], wc.x, acc);
            h[p][o] = relu2(acc);
        }
    }
#pragma unroll
    for (int p = 0; p < PAIRS; p++)
#pragma unroll
        for (int o = 0; o < 5; o++) a[p][o] = h[p][o];
}

__global__ __launch_bounds__(NTHREADS, 4) void mlp_kernel(
    const float4* __restrict__ x, float4* __restrict__ out,
    const float* __restrict__ W0, const float* __restrict__ b0,
    const float* __restrict__ W1, const float* __restrict__ b1,
    const float* __restrict__ W2, const float* __restrict__ b2,
    const float* __restrict__ W3, const float* __restrict__ b3,
    const float* __restrict__ W4, const float* __restrict__ b4,
    const float* __restrict__ W5, const float* __restrict__ b5) {
    __shared__ __align__(16) u64 sw[W_TOTAL];
    const int t = threadIdx.x;
    const int idx = blockIdx.x * NTHREADS + t;  // 0..CHUNK-1

    // precompute row base pointers once; loads become [R+0]/[R+16]
    const float4* xp = x + 2u * (unsigned)idx;

    // front-batch input loads (independent of the weight table)
    float4 xr0[ROWS_PER_THREAD], xr1[ROWS_PER_THREAD];
#pragma unroll
    for (int r = 0; r < ROWS_PER_THREAD; r++) {
        const float4* xr = xp + (size_t)r * (2 * CHUNK);
        xr0[r] = __ldg(xr);
        xr1[r] = __ldg(xr + 1);
    }

    // in-block weight prep: fuse layer0 into layer1, build padded packed table
    if (t < W_TOTAL) {
        float v = table_entry(t, W0, b0, W1, b1, W2, b2, W3, b3, W4, b4, W5, b5);
        sw[t] = pack1(v);
    }
    __syncthreads();

    // ---- stage 1: fused layer01 (8 -> relu(5)) ----
    u64 a[PAIRS][5];
#pragma unroll
    for (int o = 0; o < 5; o++) {
        ulonglong2 wa = *reinterpret_cast<const ulonglong2*>(sw + OFF_FW + o * 10);
        ulonglong2 wb = *reinterpret_cast<const ulonglong2*>(sw + OFF_FW + o * 10 + 2);
        ulonglong2 wc = *reinterpret_cast<const ulonglong2*>(sw + OFF_FW + o * 10 + 4);
        ulonglong2 wd = *reinterpret_cast<const ulonglong2*>(sw + OFF_FW + o * 10 + 6);
        ulonglong2 we = *reinterpret_cast<const ulonglong2*>(sw + OFF_FW + o * 10 + 8);
#pragma unroll
        for (int p = 0; p < PAIRS; p++) {
            const int ra = 2 * p, rb = 2 * p + 1;
            u64 acc = we.x;  // bias
            acc = fma2(pack2(xr0[ra].x, xr0[rb].x), wa.x, acc);
            acc = fma2(pack2(xr0[ra].y, xr0[rb].y), wa.y, acc);
            acc = fma2(pack2(xr0[ra].z, xr0[rb].z), wb.x, acc);
            acc = fma2(pack2(xr0[ra].w, xr0[rb].w), wb.y, acc);
            acc = fma2(pack2(xr1[ra].x, xr1[rb].x), wc.x, acc);
            acc = fma2(pack2(xr1[ra].y, xr1[rb].y), wc.y, acc);
            acc = fma2(pack2(xr1[ra].z, xr1[rb].z), wd.x, acc);
            acc = fma2(pack2(xr1[ra].w, xr1[rb].w), wd.y, acc);
            a[p][o] = relu2(acc);
        }
    }

    // ---- stages 2..4: hidden layers ----
    hidden_stage(a, sw, OFF_W2);
    hidden_stage(a, sw, OFF_W3);
    hidden_stage(a, sw, OFF_W4);

    // ---- stage 5: output layer (5 -> relu(4)) + streaming store ----
    float res[ROWS_PER_THREAD][4];
#pragma unroll
    for (int o = 0; o < 4; o++) {
        ulonglong2 wa = *reinterpret_cast<const ulonglong2*>(sw + OFF_W5 + o * 6);
        ulonglong2 wb = *reinterpret_cast<const ulonglong2*>(sw + OFF_W5 + o * 6 + 2);
        ulonglong2 wc = *reinterpret_cast<const ulonglong2*>(sw + OFF_W5 + o * 6 + 4);
#pragma unroll
        for (int p = 0; p < PAIRS; p++) {
            u64 acc = wc.y;  // bias
            acc = fma2(a[p][0], wa.x, acc);
            acc = fma2(a[p][1], wa.y, acc);
            acc = fma2(a[p][2], wb.x, acc);
            acc = fma2(a[p][3], wb.y, acc);
            acc = fma2(a[p][4], wc.x, acc);
            acc = relu2(acc);
            unpack2(acc, res[2 * p][o], res[2 * p + 1][o]);
        }
    }
    float4* op = out + idx;
#pragma unroll
    for (int r = 0; r < ROWS_PER_THREAD; r++) {
        __stcs(op + (size_t)r * CHUNK,
               make_float4(res[r][0], res[r][1], res[r][2], res[r][3]));
    }
}

extern "C" void kernel_launch(void* const* d_in, const int* in_sizes, int n_in,
                              void* d_out, int out_size) {
    const float* x  = (const float*)d_in[0];
    const float* W0 = (const float*)d_in[1];
    const float* b0 = (const float*)d_in[2];
    const float* W1 = (const float*)d_in[3];
    const float* b1 = (const float*)d_in[4];
    const float* W2 = (const float*)d_in[5];
    const float* b2 = (const float*)d_in[6];
    const float* W3 = (const float*)d_in[7];
    const float* b3 = (const float*)d_in[8];
    const float* W4 = (const float*)d_in[9];
    const float* b4 = (const float*)d_in[10];
    const float* W5 = (const float*)d_in[11];
    const float* b5 = (const float*)d_in[12];

    const int grid = (BATCH / ROWS_PER_THREAD) / NTHREADS;  // 2048
    mlp_kernel<<<grid, NTHREADS>>>((const float4*)x, (float4*)d_out,
                                   W0, b0, W1, b1, W2, b2, W3, b3, W4, b4, W5, b5);
}

// round 6
// speedup vs baseline: 1.0707x; 1.0707x over previous
#include <cuda_runtime.h>

typedef unsigned long long u64;

// ---------------- packed f32x2 helpers (Blackwell FFMA2) ----------------
__device__ __forceinline__ u64 pack2(float a, float b) {
    u64 r; asm("mov.b64 %0, {%1, %2};" : "=l"(r) : "f"(a), "f"(b)); return r;
}
__device__ __forceinline__ u64 pack1(float a) { return pack2(a, a); }
__device__ __forceinline__ void unpack2(u64 v, float& a, float& b) {
    asm("mov.b64 {%0, %1}, %2;" : "=f"(a), "=f"(b) : "l"(v));
}
__device__ __forceinline__ u64 fma2(u64 a, u64 b, u64 c) {
    u64 d; asm("fma.rn.f32x2 %0, %1, %2, %3;" : "=l"(d) : "l"(a), "l"(b), "l"(c));
    return d;
}
__device__ __forceinline__ u64 relu2(u64 v) {
    float a, b; unpack2(v, a, b);
    a = fmaxf(a, 0.0f); b = fmaxf(b, 0.0f);
    return pack2(a, b);
}

// ---------------- constants ----------------
#define NTHREADS 128
#define ROWS_PER_THREAD 4
#define PAIRS 2
static constexpr int BATCH = 2097152;
static constexpr int CHUNK = BATCH / ROWS_PER_THREAD;  // 524288

// ---------------- padded weight table (u64 indices), bias embedded -------
// stage1 fused: 5 rows, stride 10: [w0..w7, b, pad]       [0,50)
// W2..W4:       5 rows, stride 6:  [w0..w4, b]            [50,80) [80,110) [110,140)
// W5:           4 rows, stride 6:  [w0..w4, b]            [140,164)
#define OFF_FW   0
#define OFF_W2   50
#define OFF_W3   80
#define OFF_W4   110
#define OFF_W5   140
#define W_TOTAL  164

// table pre-packed as duplicated-halves u64 (ready for fma.rn.f32x2)
__device__ u64 g_wp[W_TOTAL];

// ---------------- prep: fuse layer0 into layer1, build packed table ------
// relu(W1 (W0 x + b0) + b1) = relu((W1 W0) x + (W1 b0 + b1))
__global__ void prep_kernel(const float* __restrict__ W0, const float* __restrict__ b0,
                            const float* __restrict__ W1, const float* __restrict__ b1,
                            const float* __restrict__ W2, const float* __restrict__ b2,
                            const float* __restrict__ W3, const float* __restrict__ b3,
                            const float* __restrict__ W4, const float* __restrict__ b4,
                            const float* __restrict__ W5, const float* __restrict__ b5) {
    const int t = threadIdx.x;
    if (t < W_TOTAL) {
        float v;
        if (t < 50) {
            int o = t / 10, k = t % 10;
            if (k < 8) {
                float s = 0.0f;
#pragma unroll
                for (int h = 0; h < 5; h++) s += W1[o * 5 + h] * W0[h * 8 + k];
                v = s;
            } else if (k == 8) {
                float s = b1[o];
#pragma unroll
                for (int h = 0; h < 5; h++) s += W1[o * 5 + h] * b0[h];
                v = s;
            } else {
                v = 0.0f;
            }
        } else if (t < 80) {
            int i = t - OFF_W2, o = i / 6, k = i % 6;
            v = (k < 5) ? W2[o * 5 + k] : b2[o];
        } else if (t < 110) {
            int i = t - OFF_W3, o = i / 6, k = i % 6;
            v = (k < 5) ? W3[o * 5 + k] : b3[o];
        } else if (t < 140) {
            int i = t - OFF_W4, o = i / 6, k = i % 6;
            v = (k < 5) ? W4[o * 5 + k] : b4[o];
        } else {
            int i = t - OFF_W5, o = i / 6, k = i % 6;
            v = (k < 5) ? W5[o * 5 + k] : b5[o];
        }
        g_wp[t] = pack1(v);
    }
    __threadfence();
    __syncthreads();
    // signal dependent grid launch (PDL); memory above is visible to waiters
    asm volatile("griddepcontrol.launch_dependents;" ::: "memory");
}

// one hidden stage (5 -> relu(5)): 3x LDS.128 per neuron row (weights+bias),
// each row applied to both pairs
__device__ __forceinline__ void hidden_stage(u64 a[PAIRS][5], const u64* sw, int woff) {
    u64 h[PAIRS][5];
#pragma unroll
    for (int o = 0; o < 5; o++) {
        ulonglong2 wa = *reinterpret_cast<const ulonglong2*>(sw + woff + o * 6);
        ulonglong2 wb = *reinterpret_cast<const ulonglong2*>(sw + woff + o * 6 + 2);
        ulonglong2 wc = *reinterpret_cast<const ulonglong2*>(sw + woff + o * 6 + 4);
#pragma unroll
        for (int p = 0; p < PAIRS; p++) {
            u64 acc = wc.y;  // bias
            acc = fma2(a[p][0], wa.x, acc);
            acc = fma2(a[p][1], wa.y, acc);
            acc = fma2(a[p][2], wb.x, acc);
            acc = fma2(a[p][3], wb.y, acc);
            acc = fma2(a[p][4], wc.x, acc);
            h[p][o] = relu2(acc);
        }
    }
#pragma unroll
    for (int p = 0; p < PAIRS; p++)
#pragma unroll
        for (int o = 0; o < 5; o++) a[p][o] = h[p][o];
}

__global__ __launch_bounds__(NTHREADS, 8) void mlp_kernel(
    const float4* __restrict__ x, float4* __restrict__ out) {
    __shared__ __align__(16) u64 sw[W_TOTAL];
    const int t = threadIdx.x;
    const int idx = blockIdx.x * NTHREADS + t;  // 0..CHUNK-1

    // front-batch input loads — independent of prep kernel's output
    const float4* xp = x + 2u * (unsigned)idx;
    float4 xr0[ROWS_PER_THREAD], xr1[ROWS_PER_THREAD];
#pragma unroll
    for (int r = 0; r < ROWS_PER_THREAD; r++) {
        const float4* xr = xp + (size_t)r * (2 * CHUNK);
        xr0[r] = __ldg(xr);
        xr1[r] = __ldg(xr + 1);
    }

    // PDL: wait for prep kernel's table to be visible, then copy to shared
    asm volatile("griddepcontrol.wait;" ::: "memory");
    if (t < W_TOTAL) sw[t] = g_wp[t];
    if (t + NTHREADS < W_TOTAL) sw[t + NTHREADS] = g_wp[t + NTHREADS];
    __syncthreads();

    // ---- stage 1: fused layer01 (8 -> relu(5)) ----
    u64 a[PAIRS][5];
#pragma unroll
    for (int o = 0; o < 5; o++) {
        ulonglong2 wa = *reinterpret_cast<const ulonglong2*>(sw + OFF_FW + o * 10);
        ulonglong2 wb = *reinterpret_cast<const ulonglong2*>(sw + OFF_FW + o * 10 + 2);
        ulonglong2 wc = *reinterpret_cast<const ulonglong2*>(sw + OFF_FW + o * 10 + 4);
        ulonglong2 wd = *reinterpret_cast<const ulonglong2*>(sw + OFF_FW + o * 10 + 6);
        ulonglong2 we = *reinterpret_cast<const ulonglong2*>(sw + OFF_FW + o * 10 + 8);
#pragma unroll
        for (int p = 0; p < PAIRS; p++) {
            const int ra = 2 * p, rb = 2 * p + 1;
            u64 acc = we.x;  // bias
            acc = fma2(pack2(xr0[ra].x, xr0[rb].x), wa.x, acc);
            acc = fma2(pack2(xr0[ra].y, xr0[rb].y), wa.y, acc);
            acc = fma2(pack2(xr0[ra].z, xr0[rb].z), wb.x, acc);
            acc = fma2(pack2(xr0[ra].w, xr0[rb].w), wb.y, acc);
            acc = fma2(pack2(xr1[ra].x, xr1[rb].x), wc.x, acc);
            acc = fma2(pack2(xr1[ra].y, xr1[rb].y), wc.y, acc);
            acc = fma2(pack2(xr1[ra].z, xr1[rb].z), wd.x, acc);
            acc = fma2(pack2(xr1[ra].w, xr1[rb].w), wd.y, acc);
            a[p][o] = relu2(acc);
        }
    }

    // ---- stages 2..4: hidden layers ----
    hidden_stage(a, sw, OFF_W2);
    hidden_stage(a, sw, OFF_W3);
    hidden_stage(a, sw, OFF_W4);

    // ---- stage 5: output layer (5 -> relu(4)) + streaming store ----
    float res[ROWS_PER_THREAD][4];
#pragma unroll
    for (int o = 0; o < 4; o++) {
        ulonglong2 wa = *reinterpret_cast<const ulonglong2*>(sw + OFF_W5 + o * 6);
        ulonglong2 wb = *reinterpret_cast<const ulonglong2*>(sw + OFF_W5 + o * 6 + 2);
        ulonglong2 wc = *reinterpret_cast<const ulonglong2*>(sw + OFF_W5 + o * 6 + 4);
#pragma unroll
        for (int p = 0; p < PAIRS; p++) {
            u64 acc = wc.y;  // bias
            acc = fma2(a[p][0], wa.x, acc);
            acc = fma2(a[p][1], wa.y, acc);
            acc = fma2(a[p][2], wb.x, acc);
            acc = fma2(a[p][3], wb.y, acc);
            acc = fma2(a[p][4], wc.x, acc);
            acc = relu2(acc);
            unpack2(acc, res[2 * p][o], res[2 * p + 1][o]);
        }
    }
    float4* op = out + idx;
#pragma unroll
    for (int r = 0; r < ROWS_PER_THREAD; r++) {
        __stcs(op + (size_t)r * CHUNK,
               make_float4(res[r][0], res[r][1], res[r][2], res[r][3]));
    }
}

extern "C" void kernel_launch(void* const* d_in, const int* in_sizes, int n_in,
                              void* d_out, int out_size) {
    const float* x  = (const float*)d_in[0];
    const float* W0 = (const float*)d_in[1];
    const float* b0 = (const float*)d_in[2];
    const float* W1 = (const float*)d_in[3];
    const float* b1 = (const float*)d_in[4];
    const float* W2 = (const float*)d_in[5];
    const float* b2 = (const float*)d_in[6];
    const float* W3 = (const float*)d_in[7];
    const float* b3 = (const float*)d_in[8];
    const float* W4 = (const float*)d_in[9];
    const float* b4 = (const float*)d_in[10];
    const float* W5 = (const float*)d_in[11];
    const float* b5 = (const float*)d_in[12];

    prep_kernel<<<1, 192>>>(W0, b0, W1, b1, W2, b2, W3, b3, W4, b4, W5, b5);

    // PDL launch: mlp_kernel may start while prep is finishing; it gates
    // itself with griddepcontrol.wait before touching g_wp.
    const float4* xv = (const float4*)x;
    float4* ov = (float4*)d_out;

    cudaLaunchConfig_t cfg = {};
    cfg.gridDim = dim3((BATCH / ROWS_PER_THREAD) / NTHREADS, 1, 1);  // 4096
    cfg.blockDim = dim3(NTHREADS, 1, 1);
    cfg.dynamicSmemBytes = 0;
    cfg.stream = 0;
    cudaLaunchAttribute attr[1];
    attr[0].id = cudaLaunchAttributeProgrammaticStreamSerialization;
    attr[0].val.programmaticStreamSerializationAllowed = 1;
    cfg.attrs = attr;
    cfg.numAttrs = 1;
    cudaLaunchKernelEx(&cfg, mlp_kernel, xv, ov);
}